// round 1
// baseline (speedup 1.0000x reference)
#include <cuda_runtime.h>
#include <cuda_bf16.h>
#include <cstddef>

// Problem dims
#define Bc 4
#define Hc 8
#define Pc 32
#define Nc 32
#define Dc 16
#define Lc 1024           // P*N
#define WINc 10
#define Ec 2
#define NFc 6
#define PREDc 96
#define SEQc 512
#define EPSc 1.1920929e-07f
#define FULLMASK 0xffffffffu

// Scratch (no cudaMalloc allowed)
__device__ float g_h0[Bc * Hc * Lc * Dc];
__device__ float g_h1[Bc * Hc * Lc * Dc];

// ---------------------------------------------------------------------------
// Attention + residual + RMSNorm.
// Block per (patch p, head h, batch b). Keys = patches p+1..min(p+9,31),
// staged in shared with row stride 20 floats (conflict-free float4 reads).
// 512 threads = 16 warps, each warp handles 2 of the 32 queries in patch p.
// ---------------------------------------------------------------------------
__global__ __launch_bounds__(512) void attn_kernel(
    const float* __restrict__ in, float* __restrict__ out,
    const float* __restrict__ log_scale, const float* __restrict__ norm_w)
{
    __shared__ float sk[288 * 20];   // keys, padded stride
    __shared__ float sq[32 * 16];    // queries
    __shared__ float snw[16];

    const int p   = blockIdx.x;
    const int hh  = blockIdx.y;
    const int b   = blockIdx.z;
    const int tid = threadIdx.x;
    const int warp = tid >> 5, lane = tid & 31;

    const float* base = in + ((size_t)(b * Hc + hh) * Lc) * Dc;
    const float* qb   = base + (size_t)p * Nc * Dc;
    const int npat = min(WINc - 1, (Pc - 1) - p);
    const int nk   = npat * Nc;

    if (tid < 128) ((float4*)sq)[tid] = ((const float4*)qb)[tid];
    if (tid < 16)  snw[tid] = norm_w[tid];
    const float* kb = base + (size_t)(p + 1) * Nc * Dc;
    for (int i = tid; i < nk * 16; i += 512)
        sk[(i >> 4) * 20 + (i & 15)] = kb[i];
    __syncthreads();

    const float scale = fminf(fmaxf(expf(log_scale[0]), 1.0f), 30.0f) * 0.25f;

    for (int qi = warp; qi < 32; qi += 16) {
        float q[16];
#pragma unroll
        for (int d = 0; d < 16; d++) q[d] = sq[qi * 16 + d];
        float acc[16];
#pragma unroll
        for (int d = 0; d < 16; d++) acc[d] = 0.f;

        if (nk > 0) {
            float s[9];
            float mx = -1e30f, mn = 1e30f;
#pragma unroll
            for (int j = 0; j < 9; j++) {
                int k = lane + (j << 5);
                if (k < nk) {
                    const float* kr = sk + k * 20;
                    float dot = 0.f;
#pragma unroll
                    for (int d = 0; d < 16; d++) dot += q[d] * kr[d];
                    s[j] = dot;
                    mx = fmaxf(mx, dot);
                    mn = fminf(mn, dot);
                } else s[j] = 0.f;
            }
#pragma unroll
            for (int o = 16; o; o >>= 1) {
                mx = fmaxf(mx, __shfl_xor_sync(FULLMASK, mx, o));
                mn = fminf(mn, __shfl_xor_sync(FULLMASK, mn, o));
            }
            float ep[9], en[9];
            float zp = 0.f, zn = 0.f;
#pragma unroll
            for (int j = 0; j < 9; j++) {
                int k = lane + (j << 5);
                bool v = (k < nk);
                ep[j] = v ? __expf(scale * (s[j] - mx)) : 0.f;
                en[j] = v ? __expf(scale * (mn - s[j])) : 0.f;
                zp += ep[j];
                zn += en[j];
            }
#pragma unroll
            for (int o = 16; o; o >>= 1) {
                zp += __shfl_xor_sync(FULLMASK, zp, o);
                zn += __shfl_xor_sync(FULLMASK, zn, o);
            }
            float izp = 1.0f / zp, izn = 1.0f / zn;
#pragma unroll
            for (int j = 0; j < 9; j++) {
                int k = lane + (j << 5);
                if (k < nk) {
                    float w = ep[j] * izp - en[j] * izn;
                    const float* kr = sk + k * 20;
#pragma unroll
                    for (int d = 0; d < 16; d++) acc[d] += w * kr[d];
                }
            }
#pragma unroll
            for (int d = 0; d < 16; d++) {
#pragma unroll
                for (int o = 16; o; o >>= 1)
                    acc[d] += __shfl_xor_sync(FULLMASK, acc[d], o);
            }
        }

        if (lane == 0) {
            float ss = 0.f;
#pragma unroll
            for (int d = 0; d < 16; d++) {
                acc[d] += q[d];              // residual
                ss += acc[d] * acc[d];
            }
            float r = rsqrtf(ss * 0.0625f + EPSc);
            float* orow = out + ((size_t)((b * Hc + hh) * Lc + p * Nc + qi)) * Dc;
#pragma unroll
            for (int d = 0; d < 16; d++) orow[d] = acc[d] * r * snw[d];
        }
    }
}

// ---------------------------------------------------------------------------
// Depthwise causal conv FFN + residual + RMSNorm (in-place, thread per row).
// up: per head h -> channels 2h,2h+1 with 3-tap causal conv along D.
// down: out[h,d] = dw0*mid0[d] + dw1*mid1[d]; exact GELU between.
// ---------------------------------------------------------------------------
__device__ __forceinline__ float gelu_exact(float x) {
    return 0.5f * x * (1.0f + erff(x * 0.70710678118654752f));
}

__global__ void ffn_kernel(float* __restrict__ hbuf,
                           const float* __restrict__ up_w,
                           const float* __restrict__ down_w,
                           const float* __restrict__ norm_w)
{
    int tid = blockIdx.x * blockDim.x + threadIdx.x;
    if (tid >= Bc * Hc * Lc) return;
    int hh = (tid >> 10) & (Hc - 1);   // (tid / L) % H

    float* row = hbuf + (size_t)tid * Dc;
    float x[16];
    {
        const float4* r4 = (const float4*)row;
        float4 a = r4[0], bq = r4[1], c = r4[2], dq = r4[3];
        x[0]=a.x;  x[1]=a.y;  x[2]=a.z;  x[3]=a.w;
        x[4]=bq.x; x[5]=bq.y; x[6]=bq.z; x[7]=bq.w;
        x[8]=c.x;  x[9]=c.y;  x[10]=c.z; x[11]=c.w;
        x[12]=dq.x;x[13]=dq.y;x[14]=dq.z;x[15]=dq.w;
    }
    const float u00 = up_w[6*hh+0], u01 = up_w[6*hh+1], u02 = up_w[6*hh+2];
    const float u10 = up_w[6*hh+3], u11 = up_w[6*hh+4], u12 = up_w[6*hh+5];
    const float dw0 = down_w[2*hh+0], dw1 = down_w[2*hh+1];

    float v[16];
    float ss = 0.f;
#pragma unroll
    for (int d = 0; d < 16; d++) {
        float xm2 = (d >= 2) ? x[d-2] : 0.f;
        float xm1 = (d >= 1) ? x[d-1] : 0.f;
        float m0 = u00 * xm2 + u01 * xm1 + u02 * x[d];
        float m1 = u10 * xm2 + u11 * xm1 + u12 * x[d];
        float y  = dw0 * gelu_exact(m0) + dw1 * gelu_exact(m1);
        v[d] = x[d] + y;
        ss += v[d] * v[d];
    }
    float r = rsqrtf(ss * 0.0625f + EPSc);
#pragma unroll
    for (int d = 0; d < 16; d++) v[d] *= r * norm_w[d];
    {
        float4* r4 = (float4*)row;
        r4[0] = make_float4(v[0],  v[1],  v[2],  v[3]);
        r4[1] = make_float4(v[4],  v[5],  v[6],  v[7]);
        r4[2] = make_float4(v[8],  v[9],  v[10], v[11]);
        r4[3] = make_float4(v[12], v[13], v[14], v[15]);
    }
}

// ---------------------------------------------------------------------------
// Head mixing + forecast projection. Block per (n, b), 512 threads.
// Stage 1: hm[d][p] = sum_h h[b,h,p*32+n,d]*mix_w[h] + mix_b   (512 values)
// Stage 2: out[b, d*6+f, n] = sum_p hm[d][p]*fore_w[f,p] + fore_b[f]
// ---------------------------------------------------------------------------
__global__ __launch_bounds__(512) void final_kernel(
    const float* __restrict__ hbuf,
    const float* __restrict__ mix_w, const float* __restrict__ mix_b,
    const float* __restrict__ fore_w, const float* __restrict__ fore_b,
    float* __restrict__ out)
{
    __shared__ float hm[16 * 32];    // [d][p]
    const int n = blockIdx.x, b = blockIdx.y;
    const int t = threadIdx.x;
    const int d = t >> 5, p = t & 31;

    float acc = mix_b[0];
#pragma unroll
    for (int h = 0; h < Hc; h++)
        acc += hbuf[((size_t)((b * Hc + h) * Lc + p * Nc + n)) * Dc + d] * mix_w[h];
    hm[d * 32 + p] = acc;
    __syncthreads();

    if (t < PREDc) {             // r = d*NF + f == t
        int dd = t / NFc, f = t - dd * NFc;
        float v = fore_b[f];
#pragma unroll
        for (int pp = 0; pp < Pc; pp++)
            v += hm[dd * 32 + pp] * fore_w[f * Pc + pp];
        out[((size_t)b * PREDc + t) * Nc + n] = v;
    }
}

__global__ void copy_kernel(const float* __restrict__ in, float* __restrict__ out, int n)
{
    int i = blockIdx.x * blockDim.x + threadIdx.x;
    if (i < n) out[i] = in[i];
}

// ---------------------------------------------------------------------------
extern "C" void kernel_launch(void* const* d_in, const int* in_sizes, int n_in,
                              void* d_out, int out_size)
{
    const float* tokens     = (const float*)d_in[0];
    const float* x_original = (const float*)d_in[1];
    const float* log_scales = (const float*)d_in[2];
    const float* attn_norm  = (const float*)d_in[3];
    const float* conv_up    = (const float*)d_in[4];
    const float* conv_down  = (const float*)d_in[5];
    const float* ffn_norm   = (const float*)d_in[6];
    const float* mix_w      = (const float*)d_in[7];
    const float* mix_b      = (const float*)d_in[8];
    const float* fore_w     = (const float*)d_in[9];
    const float* fore_b     = (const float*)d_in[10];
    float* out = (float*)d_out;

    float *h0, *h1;
    cudaGetSymbolAddress((void**)&h0, g_h0);
    cudaGetSymbolAddress((void**)&h1, g_h1);

    dim3 ag(Pc, Hc, Bc);   // (patch, head, batch)

    // layer 0
    attn_kernel<<<ag, 512>>>(tokens, h0, log_scales + 0, attn_norm + 0);
    ffn_kernel<<<(Bc*Hc*Lc + 255) / 256, 256>>>(h0, conv_up + 0, conv_down + 0, ffn_norm + 0);
    // layer 1
    attn_kernel<<<ag, 512>>>(h0, h1, log_scales + 1, attn_norm + Dc);
    ffn_kernel<<<(Bc*Hc*Lc + 255) / 256, 256>>>(h1, conv_up + 2*Hc*3, conv_down + Hc*2, ffn_norm + Dc);
    // head-mix + forecast
    final_kernel<<<dim3(Nc, Bc), 512>>>(h1, mix_w, mix_b, fore_w, fore_b, out);

    // tuple output: (forecast, x_original)
    const int fc = Bc * PREDc * Nc;        // 12288
    const int xo = Bc * SEQc * Nc;         // 65536
    if (out_size >= fc + xo)
        copy_kernel<<<(xo + 255) / 256, 256>>>(x_original, out + fc, xo);
}

// round 3
// speedup vs baseline: 1.1080x; 1.1080x over previous
#include <cuda_runtime.h>
#include <cuda_bf16.h>
#include <cstddef>

#define Bc 4
#define Hc 8
#define Pc 32
#define Nc 32
#define Dc 16
#define Lc 1024
#define WINc 10
#define NFc 6
#define PREDc 96
#define SEQc 512
#define EPSc 1.1920929e-07f
#define FULLMASK 0xffffffffu

__device__ float g_h0[Bc * Hc * Lc * Dc];
__device__ float g_h1[Bc * Hc * Lc * Dc];

__device__ __forceinline__ float wsum(float v) {
#pragma unroll
    for (int o = 16; o; o >>= 1) v += __shfl_xor_sync(FULLMASK, v, o);
    return v;
}
__device__ __forceinline__ float wmax(float v) {
#pragma unroll
    for (int o = 16; o; o >>= 1) v = fmaxf(v, __shfl_xor_sync(FULLMASK, v, o));
    return v;
}
__device__ __forceinline__ float wmin(float v) {
#pragma unroll
    for (int o = 16; o; o >>= 1) v = fminf(v, __shfl_xor_sync(FULLMASK, v, o));
    return v;
}

__device__ __forceinline__ float gelu_exact(float x) {
    return 0.5f * x * (1.0f + erff(x * 0.70710678118654752f));
}

// ---------------------------------------------------------------------------
// Fused: signed banded attention + residual + RMSNorm + conv-FFN + RMSNorm.
// Block per (patch p, head h, batch b); 256 threads = 8 warps.
// Each warp computes 4 queries (lane = key). Normed rows -> shared -> FFN.
// ---------------------------------------------------------------------------
__global__ __launch_bounds__(256) void attn_ffn_kernel(
    const float* __restrict__ in, float* __restrict__ out,
    const float* __restrict__ log_scale, const float* __restrict__ attn_nw,
    const float* __restrict__ up_w, const float* __restrict__ down_w,
    const float* __restrict__ ffn_nw)
{
    __shared__ float sk[288 * 20];     // keys, padded stride (conflict-free LDS.128)
    __shared__ float sq[32 * 16];      // queries
    __shared__ float snw[16];          // attn norm weight
    __shared__ float sout[32 * 17];    // attn-normed rows for FFN stage

    const int p   = blockIdx.x;
    const int hh  = blockIdx.y;
    const int b   = blockIdx.z;
    const int tid = threadIdx.x;
    const int warp = tid >> 5, lane = tid & 31;

    const float* base = in + ((size_t)(b * Hc + hh) * Lc) * Dc;
    const float* qb   = base + (size_t)p * Nc * Dc;
    const int npat = min(WINc - 1, (Pc - 1) - p);
    const int nk   = npat * Nc;

    if (tid < 128) ((float4*)sq)[tid] = ((const float4*)qb)[tid];
    if (tid < 16)  snw[tid] = attn_nw[tid];
    const float4* kb4 = (const float4*)(base + (size_t)(p + 1) * Nc * Dc);
    for (int i = tid; i < nk * 4; i += 256) {
        int key = i >> 2, chunk = i & 3;
        *(float4*)(sk + key * 20 + chunk * 4) = kb4[i];
    }
    __syncthreads();

    const float scale = fminf(fmaxf(__expf(log_scale[0]), 1.0f), 30.0f) * 0.25f;

    for (int qi = warp; qi < 32; qi += 8) {
        float q[16];
#pragma unroll
        for (int d = 0; d < 16; d++) q[d] = sq[qi * 16 + d];
        float acc[16];
#pragma unroll
        for (int d = 0; d < 16; d++) acc[d] = 0.f;

        if (nk > 0) {
            float s[9];
            float mx = -1e30f, mn = 1e30f;
#pragma unroll
            for (int j = 0; j < 9; j++) {
                int k = lane + (j << 5);
                if (k < nk) {
                    const float4* kr4 = (const float4*)(sk + k * 20);
                    float4 k0 = kr4[0], k1 = kr4[1], k2 = kr4[2], k3 = kr4[3];
                    float dot = q[0]*k0.x + q[1]*k0.y + q[2]*k0.z + q[3]*k0.w
                              + q[4]*k1.x + q[5]*k1.y + q[6]*k1.z + q[7]*k1.w
                              + q[8]*k2.x + q[9]*k2.y + q[10]*k2.z + q[11]*k2.w
                              + q[12]*k3.x + q[13]*k3.y + q[14]*k3.z + q[15]*k3.w;
                    s[j] = dot;
                    mx = fmaxf(mx, dot);
                    mn = fminf(mn, dot);
                } else s[j] = 0.f;
            }
            mx = wmax(mx);
            mn = wmin(mn);

            float w[9];
            float zp = 0.f, zn = 0.f;
#pragma unroll
            for (int j = 0; j < 9; j++) {
                int k = lane + (j << 5);
                bool v = (k < nk);
                float ep = v ? __expf(scale * (s[j] - mx)) : 0.f;
                float en = v ? __expf(scale * (mn - s[j])) : 0.f;
                zp += ep; zn += en;
                s[j] = ep;
                w[j] = en;
            }
            zp = wsum(zp);
            zn = wsum(zn);
            float izp = 1.0f / zp, izn = 1.0f / zn;
#pragma unroll
            for (int j = 0; j < 9; j++) {
                int k = lane + (j << 5);
                if (k < nk) {
                    float ww = s[j] * izp - w[j] * izn;
                    const float4* kr4 = (const float4*)(sk + k * 20);
                    float4 k0 = kr4[0], k1 = kr4[1], k2 = kr4[2], k3 = kr4[3];
                    acc[0]  += ww*k0.x;  acc[1]  += ww*k0.y;  acc[2]  += ww*k0.z;  acc[3]  += ww*k0.w;
                    acc[4]  += ww*k1.x;  acc[5]  += ww*k1.y;  acc[6]  += ww*k1.z;  acc[7]  += ww*k1.w;
                    acc[8]  += ww*k2.x;  acc[9]  += ww*k2.y;  acc[10] += ww*k2.z;  acc[11] += ww*k2.w;
                    acc[12] += ww*k3.x;  acc[13] += ww*k3.y;  acc[14] += ww*k3.z;  acc[15] += ww*k3.w;
                }
            }
#pragma unroll
            for (int d = 0; d < 16; d++) acc[d] = wsum(acc[d]);
        }

        if (lane == 0) {
            float ss = 0.f;
#pragma unroll
            for (int d = 0; d < 16; d++) {
                acc[d] += q[d];
                ss += acc[d] * acc[d];
            }
            float r = rsqrtf(ss * 0.0625f + EPSc);
#pragma unroll
            for (int d = 0; d < 16; d++) sout[qi * 17 + d] = acc[d] * r * snw[d];
        }
    }
    __syncthreads();

    // Stage 2: row-local conv FFN + residual + RMSNorm, one thread per row.
    if (tid < 32) {
        float x[16];
#pragma unroll
        for (int d = 0; d < 16; d++) x[d] = sout[tid * 17 + d];

        const float u00 = up_w[6*hh+0], u01 = up_w[6*hh+1], u02 = up_w[6*hh+2];
        const float u10 = up_w[6*hh+3], u11 = up_w[6*hh+4], u12 = up_w[6*hh+5];
        const float dw0 = down_w[2*hh+0], dw1 = down_w[2*hh+1];

        float v[16];
        float ss = 0.f;
#pragma unroll
        for (int d = 0; d < 16; d++) {
            float xm2 = (d >= 2) ? x[d-2] : 0.f;
            float xm1 = (d >= 1) ? x[d-1] : 0.f;
            float m0 = u00 * xm2 + u01 * xm1 + u02 * x[d];
            float m1 = u10 * xm2 + u11 * xm1 + u12 * x[d];
            float y  = dw0 * gelu_exact(m0) + dw1 * gelu_exact(m1);
            v[d] = x[d] + y;
            ss += v[d] * v[d];
        }
        float r = rsqrtf(ss * 0.0625f + EPSc);
        float nv[16];
#pragma unroll
        for (int d = 0; d < 16; d++) nv[d] = v[d] * r * ffn_nw[d];
        float4* orow = (float4*)(out + ((size_t)((b * Hc + hh) * Lc + p * Nc + tid)) * Dc);
        orow[0] = make_float4(nv[0],  nv[1],  nv[2],  nv[3]);
        orow[1] = make_float4(nv[4],  nv[5],  nv[6],  nv[7]);
        orow[2] = make_float4(nv[8],  nv[9],  nv[10], nv[11]);
        orow[3] = make_float4(nv[12], nv[13], nv[14], nv[15]);
    }
}

// ---------------------------------------------------------------------------
// Head mixing + forecast projection (z=0) fused with x_original copy (z=1).
// ---------------------------------------------------------------------------
__global__ __launch_bounds__(512) void final_copy_kernel(
    const float* __restrict__ hbuf,
    const float* __restrict__ mix_w, const float* __restrict__ mix_b,
    const float* __restrict__ fore_w, const float* __restrict__ fore_b,
    const float* __restrict__ x_original,
    float* __restrict__ out)
{
    const int t = threadIdx.x;
    if (blockIdx.z == 1) {
        // copy 65536 floats = 16384 float4 across 128 blocks x 512 threads
        int idx = (blockIdx.y * Nc + blockIdx.x) * 512 + t;
        if (idx < (Bc * SEQc * Nc) / 4)
            ((float4*)(out + Bc * PREDc * Nc))[idx] = ((const float4*)x_original)[idx];
        return;
    }

    __shared__ float hm[16 * 32];    // [d][p]
    const int n = blockIdx.x, b = blockIdx.y;
    const int d = t >> 5, p = t & 31;

    float acc = mix_b[0];
#pragma unroll
    for (int h = 0; h < Hc; h++)
        acc += hbuf[((size_t)((b * Hc + h) * Lc + p * Nc + n)) * Dc + d] * mix_w[h];
    hm[d * 32 + p] = acc;
    __syncthreads();

    if (t < PREDc) {
        int dd = t / NFc, f = t - dd * NFc;
        float v = fore_b[f];
#pragma unroll
        for (int pp = 0; pp < Pc; pp++)
            v += hm[dd * 32 + pp] * fore_w[f * Pc + pp];
        out[((size_t)b * PREDc + t) * Nc + n] = v;
    }
}

// ---------------------------------------------------------------------------
extern "C" void kernel_launch(void* const* d_in, const int* in_sizes, int n_in,
                              void* d_out, int out_size)
{
    const float* tokens     = (const float*)d_in[0];
    const float* x_original = (const float*)d_in[1];
    const float* log_scales = (const float*)d_in[2];
    const float* attn_norm  = (const float*)d_in[3];
    const float* conv_up    = (const float*)d_in[4];
    const float* conv_down  = (const float*)d_in[5];
    const float* ffn_norm   = (const float*)d_in[6];
    const float* mix_w      = (const float*)d_in[7];
    const float* mix_b      = (const float*)d_in[8];
    const float* fore_w     = (const float*)d_in[9];
    const float* fore_b     = (const float*)d_in[10];
    float* out = (float*)d_out;

    float *h0, *h1;
    cudaGetSymbolAddress((void**)&h0, g_h0);
    cudaGetSymbolAddress((void**)&h1, g_h1);

    dim3 ag(Pc, Hc, Bc);

    attn_ffn_kernel<<<ag, 256>>>(tokens, h0, log_scales + 0, attn_norm + 0,
                                 conv_up + 0, conv_down + 0, ffn_norm + 0);
    attn_ffn_kernel<<<ag, 256>>>(h0, h1, log_scales + 1, attn_norm + Dc,
                                 conv_up + 2*Hc*3, conv_down + Hc*2, ffn_norm + Dc);

    const int fc = Bc * PREDc * Nc;   // 12288
    const int xo = Bc * SEQc * Nc;    // 65536
    dim3 fg(Nc, Bc, (out_size >= fc + xo) ? 2 : 1);
    final_copy_kernel<<<fg, 512>>>(h1, mix_w, mix_b, fore_w, fore_b, x_original, out);
}

// round 4
// speedup vs baseline: 1.8301x; 1.6516x over previous
#include <cuda_runtime.h>
#include <cuda_bf16.h>
#include <cstddef>

#define Bc 4
#define Hc 8
#define Pc 32
#define Nc 32
#define Dc 16
#define Lc 1024
#define WINc 10
#define NFc 6
#define PREDc 96
#define SEQc 512
#define EPSc 1.1920929e-07f
#define FULLMASK 0xffffffffu

__device__ float g_h0[Bc * Hc * Lc * Dc];
__device__ float g_h1[Bc * Hc * Lc * Dc];

__device__ __forceinline__ float gelu_exact(float x) {
    return 0.5f * x * (1.0f + erff(x * 0.70710678118654752f));
}

// ---------------------------------------------------------------------------
// Fused layer kernel: signed banded attention + residual + RMSNorm + conv-FFN
// + residual + RMSNorm.  Block per (patch p, head h, batch b); 256 thr = 8 warps.
// lane = query (q row + accumulators in registers). Warps split the <=288 keys
// (stride 8); key rows are uniform-broadcast LDG (each row read once/block).
// Signed softmax WITHOUT max-subtraction (|scale*s| <= ~12, fp32-safe), so
// partial states merge by pure addition through one smem array.
// ---------------------------------------------------------------------------
__global__ __launch_bounds__(256) void attn_ffn_kernel(
    const float* __restrict__ in, float* __restrict__ out,
    const float* __restrict__ log_scale, const float* __restrict__ attn_nw,
    const float* __restrict__ up_w, const float* __restrict__ down_w,
    const float* __restrict__ ffn_nw)
{
    // part[w][slot][q] : slots 0..15 acc_p, 16..31 acc_n, 32 zp, 33 zn
    __shared__ float part[8 * 34 * 32];

    const int p    = blockIdx.x;
    const int hh   = blockIdx.y;
    const int b    = blockIdx.z;
    const int tid  = threadIdx.x;
    const int warp = tid >> 5, lane = tid & 31;

    const float* base = in + ((size_t)(b * Hc + hh) * Lc) * Dc;
    const float* qb   = base + (size_t)p * Nc * Dc;         // 32 query rows
    const float* kb   = base + (size_t)(p + 1) * Nc * Dc;   // key rows
    const int npat = min(WINc - 1, (Pc - 1) - p);
    const int nk   = npat * Nc;

    const float scale = fminf(fmaxf(__expf(log_scale[0]), 1.0f), 30.0f) * 0.25f;

    // Each lane owns query row `lane`
    float q[16];
    {
        const float4* q4 = (const float4*)(qb + (size_t)lane * Dc);
        float4 a = q4[0], b4 = q4[1], c = q4[2], d4 = q4[3];
        q[0]=a.x; q[1]=a.y; q[2]=a.z; q[3]=a.w;
        q[4]=b4.x; q[5]=b4.y; q[6]=b4.z; q[7]=b4.w;
        q[8]=c.x; q[9]=c.y; q[10]=c.z; q[11]=c.w;
        q[12]=d4.x; q[13]=d4.y; q[14]=d4.z; q[15]=d4.w;
    }

    float accp[16], accn[16];
#pragma unroll
    for (int d = 0; d < 16; d++) { accp[d] = 0.f; accn[d] = 0.f; }
    float zp = 0.f, zn = 0.f;

    for (int k = warp; k < nk; k += 8) {
        const float4* kr = (const float4*)(kb + (size_t)k * Dc);
        float4 k0 = kr[0], k1 = kr[1], k2 = kr[2], k3 = kr[3];
        float dot = q[0]*k0.x + q[1]*k0.y + q[2]*k0.z + q[3]*k0.w
                  + q[4]*k1.x + q[5]*k1.y + q[6]*k1.z + q[7]*k1.w
                  + q[8]*k2.x + q[9]*k2.y + q[10]*k2.z + q[11]*k2.w
                  + q[12]*k3.x + q[13]*k3.y + q[14]*k3.z + q[15]*k3.w;
        float sp = scale * dot;
        float ep = __expf(sp);
        float en = __expf(-sp);
        zp += ep; zn += en;
        accp[0]  += ep*k0.x; accp[1]  += ep*k0.y; accp[2]  += ep*k0.z; accp[3]  += ep*k0.w;
        accp[4]  += ep*k1.x; accp[5]  += ep*k1.y; accp[6]  += ep*k1.z; accp[7]  += ep*k1.w;
        accp[8]  += ep*k2.x; accp[9]  += ep*k2.y; accp[10] += ep*k2.z; accp[11] += ep*k2.w;
        accp[12] += ep*k3.x; accp[13] += ep*k3.y; accp[14] += ep*k3.z; accp[15] += ep*k3.w;
        accn[0]  += en*k0.x; accn[1]  += en*k0.y; accn[2]  += en*k0.z; accn[3]  += en*k0.w;
        accn[4]  += en*k1.x; accn[5]  += en*k1.y; accn[6]  += en*k1.z; accn[7]  += en*k1.w;
        accn[8]  += en*k2.x; accn[9]  += en*k2.y; accn[10] += en*k2.z; accn[11] += en*k2.w;
        accn[12] += en*k3.x; accn[13] += en*k3.y; accn[14] += en*k3.z; accn[15] += en*k3.w;
    }

    // dump partial state (conflict-free: lane-contiguous)
    {
        float* pw = part + warp * (34 * 32);
#pragma unroll
        for (int d = 0; d < 16; d++) {
            pw[d * 32 + lane]        = accp[d];
            pw[(16 + d) * 32 + lane] = accn[d];
        }
        pw[32 * 32 + lane] = zp;
        pw[33 * 32 + lane] = zn;
    }
    __syncthreads();

    // merge 8 warps' partials by addition (each i owned by one thread)
    for (int i = tid; i < 34 * 32; i += 256) {
        float s = part[i];
#pragma unroll
        for (int w = 1; w < 8; w++) s += part[w * (34 * 32) + i];
        part[i] = s;
    }
    __syncthreads();

    // Finalize: 32 threads, thread = query row. Attn out + residual + RMSNorm,
    // then row-local conv FFN + residual + RMSNorm, write to global.
    if (tid < 32) {
        float x[16];
        float zpt = part[32 * 32 + tid];
        float znt = part[33 * 32 + tid];
        if (nk > 0) {
            float izp = 1.0f / zpt, izn = 1.0f / znt;
#pragma unroll
            for (int d = 0; d < 16; d++)
                x[d] = part[d * 32 + tid] * izp - part[(16 + d) * 32 + tid] * izn;
        } else {
#pragma unroll
            for (int d = 0; d < 16; d++) x[d] = 0.f;
        }
        // residual with own q row
        const float4* q4 = (const float4*)(qb + (size_t)tid * Dc);
        float4 a = q4[0], b4 = q4[1], c = q4[2], d4 = q4[3];
        float qq[16] = {a.x,a.y,a.z,a.w,b4.x,b4.y,b4.z,b4.w,
                        c.x,c.y,c.z,c.w,d4.x,d4.y,d4.z,d4.w};
        float ss = 0.f;
#pragma unroll
        for (int d = 0; d < 16; d++) { x[d] += qq[d]; ss += x[d] * x[d]; }
        float r = rsqrtf(ss * 0.0625f + EPSc);
#pragma unroll
        for (int d = 0; d < 16; d++) x[d] = x[d] * r * attn_nw[d];

        // conv FFN
        const float u00 = up_w[6*hh+0], u01 = up_w[6*hh+1], u02 = up_w[6*hh+2];
        const float u10 = up_w[6*hh+3], u11 = up_w[6*hh+4], u12 = up_w[6*hh+5];
        const float dw0 = down_w[2*hh+0], dw1 = down_w[2*hh+1];

        float v[16];
        ss = 0.f;
#pragma unroll
        for (int d = 0; d < 16; d++) {
            float xm2 = (d >= 2) ? x[d-2] : 0.f;
            float xm1 = (d >= 1) ? x[d-1] : 0.f;
            float m0 = u00 * xm2 + u01 * xm1 + u02 * x[d];
            float m1 = u10 * xm2 + u11 * xm1 + u12 * x[d];
            float y  = dw0 * gelu_exact(m0) + dw1 * gelu_exact(m1);
            v[d] = x[d] + y;
            ss += v[d] * v[d];
        }
        r = rsqrtf(ss * 0.0625f + EPSc);
        float nv[16];
#pragma unroll
        for (int d = 0; d < 16; d++) nv[d] = v[d] * r * ffn_nw[d];
        float4* orow = (float4*)(out + ((size_t)((b * Hc + hh) * Lc + p * Nc + tid)) * Dc);
        orow[0] = make_float4(nv[0],  nv[1],  nv[2],  nv[3]);
        orow[1] = make_float4(nv[4],  nv[5],  nv[6],  nv[7]);
        orow[2] = make_float4(nv[8],  nv[9],  nv[10], nv[11]);
        orow[3] = make_float4(nv[12], nv[13], nv[14], nv[15]);
    }
}

// ---------------------------------------------------------------------------
// Head mixing + forecast projection (z=0) fused with x_original copy (z=1).
// ---------------------------------------------------------------------------
__global__ __launch_bounds__(512) void final_copy_kernel(
    const float* __restrict__ hbuf,
    const float* __restrict__ mix_w, const float* __restrict__ mix_b,
    const float* __restrict__ fore_w, const float* __restrict__ fore_b,
    const float* __restrict__ x_original,
    float* __restrict__ out)
{
    const int t = threadIdx.x;
    if (blockIdx.z == 1) {
        int idx = (blockIdx.y * Nc + blockIdx.x) * 512 + t;
        if (idx < (Bc * SEQc * Nc) / 4)
            ((float4*)(out + Bc * PREDc * Nc))[idx] = ((const float4*)x_original)[idx];
        return;
    }

    __shared__ float hm[16 * 32];    // [d][p]
    const int n = blockIdx.x, b = blockIdx.y;
    const int d = t >> 5, p = t & 31;

    float acc = mix_b[0];
#pragma unroll
    for (int h = 0; h < Hc; h++)
        acc += hbuf[((size_t)((b * Hc + h) * Lc + p * Nc + n)) * Dc + d] * mix_w[h];
    hm[d * 32 + p] = acc;
    __syncthreads();

    if (t < PREDc) {
        int dd = t / NFc, f = t - dd * NFc;
        float v = fore_b[f];
#pragma unroll
        for (int pp = 0; pp < Pc; pp++)
            v += hm[dd * 32 + pp] * fore_w[f * Pc + pp];
        out[((size_t)b * PREDc + t) * Nc + n] = v;
    }
}

// ---------------------------------------------------------------------------
extern "C" void kernel_launch(void* const* d_in, const int* in_sizes, int n_in,
                              void* d_out, int out_size)
{
    const float* tokens     = (const float*)d_in[0];
    const float* x_original = (const float*)d_in[1];
    const float* log_scales = (const float*)d_in[2];
    const float* attn_norm  = (const float*)d_in[3];
    const float* conv_up    = (const float*)d_in[4];
    const float* conv_down  = (const float*)d_in[5];
    const float* ffn_norm   = (const float*)d_in[6];
    const float* mix_w      = (const float*)d_in[7];
    const float* mix_b      = (const float*)d_in[8];
    const float* fore_w     = (const float*)d_in[9];
    const float* fore_b     = (const float*)d_in[10];
    float* out = (float*)d_out;

    float *h0, *h1;
    cudaGetSymbolAddress((void**)&h0, g_h0);
    cudaGetSymbolAddress((void**)&h1, g_h1);

    dim3 ag(Pc, Hc, Bc);

    attn_ffn_kernel<<<ag, 256>>>(tokens, h0, log_scales + 0, attn_norm + 0,
                                 conv_up + 0, conv_down + 0, ffn_norm + 0);
    attn_ffn_kernel<<<ag, 256>>>(h0, h1, log_scales + 1, attn_norm + Dc,
                                 conv_up + 2*Hc*3, conv_down + Hc*2, ffn_norm + Dc);

    const int fc = Bc * PREDc * Nc;   // 12288
    const int xo = Bc * SEQc * Nc;    // 65536
    dim3 fg(Nc, Bc, (out_size >= fc + xo) ? 2 : 1);
    final_copy_kernel<<<fg, 512>>>(h1, mix_w, mix_b, fore_w, fore_b, x_original, out);
}

// round 5
// speedup vs baseline: 1.8884x; 1.0319x over previous
#include <cuda_runtime.h>
#include <cuda_bf16.h>
#include <cstddef>

#define Bc 4
#define Hc 8
#define Pc 32
#define Nc 32
#define Dc 16
#define Lc 1024
#define WINc 10
#define NFc 6
#define PREDc 96
#define SEQc 512
#define EPSc 1.1920929e-07f
#define FULLMASK 0xffffffffu
#define LOG2E 1.4426950408889634f

__device__ float g_h0[Bc * Hc * Lc * Dc];
__device__ float g_h1[Bc * Hc * Lc * Dc];

typedef unsigned long long u64;

// ---- packed f32x2 helpers (Blackwell FFMA2 path; ptxas only emits via PTX) ----
__device__ __forceinline__ void ffma2(u64 &d, u64 a, u64 b, u64 c) {
    asm("fma.rn.f32x2 %0, %1, %2, %3;" : "=l"(d) : "l"(a), "l"(b), "l"(c));
}
__device__ __forceinline__ void add2(u64 &d, u64 a, u64 b) {
    asm("add.rn.f32x2 %0, %1, %2;" : "=l"(d) : "l"(a), "l"(b));
}
__device__ __forceinline__ u64 pack2(float lo, float hi) {
    u64 r; asm("mov.b64 %0, {%1, %2};" : "=l"(r) : "f"(lo), "f"(hi)); return r;
}
__device__ __forceinline__ void unpack2(u64 v, float &lo, float &hi) {
    asm("mov.b64 {%0, %1}, %2;" : "=f"(lo), "=f"(hi) : "l"(v));
}
__device__ __forceinline__ float ex2(float x) {
    float r; asm("ex2.approx.f32 %0, %1;" : "=f"(r) : "f"(x)); return r;
}
__device__ __forceinline__ float gelu_exact(float x) {
    return 0.5f * x * (1.0f + erff(x * 0.70710678118654752f));
}

// ---------------------------------------------------------------------------
// Fused layer: signed banded attention + residual + RMSNorm + conv-FFN
// + residual + RMSNorm. Block per (p,h,b); 256 thr = 8 warps.
// lane = query (q + accumulators in registers, all packed f32x2).
// Warps split keys stride-8; key rows are uniform-broadcast LDG.
// One-pass signed softmax without max-subtraction (|scale*s| small, fp32-safe);
// partials merge by addition through smem.
// ---------------------------------------------------------------------------
__global__ __launch_bounds__(256) void attn_ffn_kernel(
    const float* __restrict__ in, float* __restrict__ out,
    const float* __restrict__ log_scale, const float* __restrict__ attn_nw,
    const float* __restrict__ up_w, const float* __restrict__ down_w,
    const float* __restrict__ ffn_nw)
{
    // part[w][slot][q] : slots 0..15 accp, 16..31 accn, 32 zp, 33 zn
    __shared__ float part[8 * 34 * 32];

    const int p    = blockIdx.x;
    const int hh   = blockIdx.y;
    const int b    = blockIdx.z;
    const int tid  = threadIdx.x;
    const int warp = tid >> 5, lane = tid & 31;

    const float* base = in + ((size_t)(b * Hc + hh) * Lc) * Dc;
    const float* qb   = base + (size_t)p * Nc * Dc;
    const float* kb   = base + (size_t)(p + 1) * Nc * Dc;
    const int npat = min(WINc - 1, (Pc - 1) - p);
    const int nk   = npat * Nc;

    const float scale = fminf(fmaxf(__expf(log_scale[0]), 1.0f), 30.0f) * 0.25f;
    const float c = scale * LOG2E;   // fold scale + log2e into q

    // Each lane owns query row `lane`: load + pre-scale + pack
    u64 q2[8];
    {
        const float4* q4 = (const float4*)(qb + (size_t)lane * Dc);
        float4 a = q4[0], b4 = q4[1], cc = q4[2], d4 = q4[3];
        q2[0] = pack2(a.x * c,  a.y * c);   q2[1] = pack2(a.z * c,  a.w * c);
        q2[2] = pack2(b4.x * c, b4.y * c);  q2[3] = pack2(b4.z * c, b4.w * c);
        q2[4] = pack2(cc.x * c, cc.y * c);  q2[5] = pack2(cc.z * c, cc.w * c);
        q2[6] = pack2(d4.x * c, d4.y * c);  q2[7] = pack2(d4.z * c, d4.w * c);
    }

    u64 accp2[8], accn2[8];
#pragma unroll
    for (int i = 0; i < 8; i++) { accp2[i] = 0ull; accn2[i] = 0ull; }
    u64 z2 = 0ull;   // (zp, zn)

    for (int k = warp; k < nk; k += 8) {
        const ulonglong2* kr = (const ulonglong2*)(kb + (size_t)k * Dc);
        ulonglong2 kA = kr[0], kB = kr[1], kC = kr[2], kD = kr[3];
        u64 k2[8] = { kA.x, kA.y, kB.x, kB.y, kC.x, kC.y, kD.x, kD.y };

        u64 dot2 = 0ull;
#pragma unroll
        for (int i = 0; i < 8; i++) ffma2(dot2, q2[i], k2[i], dot2);
        float dlo, dhi; unpack2(dot2, dlo, dhi);
        float dot = dlo + dhi;                  // = log2e*scale*(q.k)
        float ep = ex2(dot);
        float en = ex2(-dot);
        add2(z2, z2, pack2(ep, en));
        u64 ep2 = pack2(ep, ep);
        u64 en2 = pack2(en, en);
#pragma unroll
        for (int i = 0; i < 8; i++) {
            ffma2(accp2[i], k2[i], ep2, accp2[i]);
            ffma2(accn2[i], k2[i], en2, accn2[i]);
        }
    }

    // dump partial state (unpack; conflict-free lane-contiguous layout)
    {
        float* pw = part + warp * (34 * 32);
#pragma unroll
        for (int i = 0; i < 8; i++) {
            float l0, h0, l1, h1;
            unpack2(accp2[i], l0, h0);
            pw[(2 * i) * 32 + lane]     = l0;
            pw[(2 * i + 1) * 32 + lane] = h0;
            unpack2(accn2[i], l1, h1);
            pw[(16 + 2 * i) * 32 + lane]     = l1;
            pw[(16 + 2 * i + 1) * 32 + lane] = h1;
        }
        float zp, zn; unpack2(z2, zp, zn);
        pw[32 * 32 + lane] = zp;
        pw[33 * 32 + lane] = zn;
    }
    __syncthreads();

    // merge 8 warps' partials by addition
    for (int i = tid; i < 34 * 32; i += 256) {
        float s = part[i];
#pragma unroll
        for (int w = 1; w < 8; w++) s += part[w * (34 * 32) + i];
        part[i] = s;
    }
    __syncthreads();

    // Finalize: 32 threads, thread = query row.
    if (tid < 32) {
        float x[16];
        if (nk > 0) {
            float izp = 1.0f / part[32 * 32 + tid];
            float izn = 1.0f / part[33 * 32 + tid];
#pragma unroll
            for (int d = 0; d < 16; d++)
                x[d] = part[d * 32 + tid] * izp - part[(16 + d) * 32 + tid] * izn;
        } else {
#pragma unroll
            for (int d = 0; d < 16; d++) x[d] = 0.f;
        }
        const float4* q4 = (const float4*)(qb + (size_t)tid * Dc);
        float4 a = q4[0], b4 = q4[1], cc = q4[2], d4 = q4[3];
        float qq[16] = {a.x,a.y,a.z,a.w,b4.x,b4.y,b4.z,b4.w,
                        cc.x,cc.y,cc.z,cc.w,d4.x,d4.y,d4.z,d4.w};
        float ss = 0.f;
#pragma unroll
        for (int d = 0; d < 16; d++) { x[d] += qq[d]; ss += x[d] * x[d]; }
        float r = rsqrtf(ss * 0.0625f + EPSc);
#pragma unroll
        for (int d = 0; d < 16; d++) x[d] = x[d] * r * attn_nw[d];

        const float u00 = up_w[6*hh+0], u01 = up_w[6*hh+1], u02 = up_w[6*hh+2];
        const float u10 = up_w[6*hh+3], u11 = up_w[6*hh+4], u12 = up_w[6*hh+5];
        const float dw0 = down_w[2*hh+0], dw1 = down_w[2*hh+1];

        float v[16];
        ss = 0.f;
#pragma unroll
        for (int d = 0; d < 16; d++) {
            float xm2 = (d >= 2) ? x[d-2] : 0.f;
            float xm1 = (d >= 1) ? x[d-1] : 0.f;
            float m0 = u00 * xm2 + u01 * xm1 + u02 * x[d];
            float m1 = u10 * xm2 + u11 * xm1 + u12 * x[d];
            float y  = dw0 * gelu_exact(m0) + dw1 * gelu_exact(m1);
            v[d] = x[d] + y;
            ss += v[d] * v[d];
        }
        r = rsqrtf(ss * 0.0625f + EPSc);
        float nv[16];
#pragma unroll
        for (int d = 0; d < 16; d++) nv[d] = v[d] * r * ffn_nw[d];
        float4* orow = (float4*)(out + ((size_t)((b * Hc + hh) * Lc + p * Nc + tid)) * Dc);
        orow[0] = make_float4(nv[0],  nv[1],  nv[2],  nv[3]);
        orow[1] = make_float4(nv[4],  nv[5],  nv[6],  nv[7]);
        orow[2] = make_float4(nv[8],  nv[9],  nv[10], nv[11]);
        orow[3] = make_float4(nv[12], nv[13], nv[14], nv[15]);
    }
}

// ---------------------------------------------------------------------------
// Head mixing + forecast projection (z=0) fused with x_original copy (z=1).
// ---------------------------------------------------------------------------
__global__ __launch_bounds__(512) void final_copy_kernel(
    const float* __restrict__ hbuf,
    const float* __restrict__ mix_w, const float* __restrict__ mix_b,
    const float* __restrict__ fore_w, const float* __restrict__ fore_b,
    const float* __restrict__ x_original,
    float* __restrict__ out)
{
    const int t = threadIdx.x;
    if (blockIdx.z == 1) {
        int idx = (blockIdx.y * Nc + blockIdx.x) * 512 + t;
        if (idx < (Bc * SEQc * Nc) / 4)
            ((float4*)(out + Bc * PREDc * Nc))[idx] = ((const float4*)x_original)[idx];
        return;
    }

    __shared__ float hm[16 * 32];
    const int n = blockIdx.x, b = blockIdx.y;
    const int d = t >> 5, p = t & 31;

    float acc = mix_b[0];
#pragma unroll
    for (int h = 0; h < Hc; h++)
        acc += hbuf[((size_t)((b * Hc + h) * Lc + p * Nc + n)) * Dc + d] * mix_w[h];
    hm[d * 32 + p] = acc;
    __syncthreads();

    if (t < PREDc) {
        int dd = t / NFc, f = t - dd * NFc;
        float v = fore_b[f];
#pragma unroll
        for (int pp = 0; pp < Pc; pp++)
            v += hm[dd * 32 + pp] * fore_w[f * Pc + pp];
        out[((size_t)b * PREDc + t) * Nc + n] = v;
    }
}

// ---------------------------------------------------------------------------
extern "C" void kernel_launch(void* const* d_in, const int* in_sizes, int n_in,
                              void* d_out, int out_size)
{
    const float* tokens     = (const float*)d_in[0];
    const float* x_original = (const float*)d_in[1];
    const float* log_scales = (const float*)d_in[2];
    const float* attn_norm  = (const float*)d_in[3];
    const float* conv_up    = (const float*)d_in[4];
    const float* conv_down  = (const float*)d_in[5];
    const float* ffn_norm   = (const float*)d_in[6];
    const float* mix_w      = (const float*)d_in[7];
    const float* mix_b      = (const float*)d_in[8];
    const float* fore_w     = (const float*)d_in[9];
    const float* fore_b     = (const float*)d_in[10];
    float* out = (float*)d_out;

    float *h0, *h1;
    cudaGetSymbolAddress((void**)&h0, g_h0);
    cudaGetSymbolAddress((void**)&h1, g_h1);

    dim3 ag(Pc, Hc, Bc);

    attn_ffn_kernel<<<ag, 256>>>(tokens, h0, log_scales + 0, attn_norm + 0,
                                 conv_up + 0, conv_down + 0, ffn_norm + 0);
    attn_ffn_kernel<<<ag, 256>>>(h0, h1, log_scales + 1, attn_norm + Dc,
                                 conv_up + 2*Hc*3, conv_down + Hc*2, ffn_norm + Dc);

    const int fc = Bc * PREDc * Nc;   // 12288
    const int xo = Bc * SEQc * Nc;    // 65536
    dim3 fg(Nc, Bc, (out_size >= fc + xo) ? 2 : 1);
    final_copy_kernel<<<fg, 512>>>(h1, mix_w, mix_b, fore_w, fore_b, x_original, out);
}